// round 15
// baseline (speedup 1.0000x reference)
#include <cuda_runtime.h>
#include <cuda_fp16.h>
#include <cstdint>

// ---------------------------------------------------------------------------
// NeRF fused MLP via mma.sync m16n8k16 (f16 in, fp32 acc), 2-term split:
// D = Ahi*Bh + Alo*Bh (rel_err 1.36e-4 measured R13/R14).
// NEW (R15): B fragments loaded DIRECTLY from a fragment-ordered __device__
// blob via LDG.64 (register double-buffered) — no W smem, no cp.async, no
// per-chunk barriers.  Blob is L2-resident (1.1 MB).  TM=64/CTA, 256 thr
// (8 warps, 2x4), 105.5 KB smem -> 2 CTAs/SM.  A (hi/lo) stays in smem with
// ldmatrix; term-major MMA; row-group epilogue barriers (named 5-6).
// ---------------------------------------------------------------------------

#define NT 256

// A: [64][280] halves, row stride 560 B (bank shift 12 -> conflict-free)
#define SA_B   560
#define A_HI   0
#define A_LO   35840
// hc f32 [64][132] (color hidden, fp32)
#define HCOFF  71680
#define SHC_B  528
#define WCOL0  105472
#define WC1O   106496
#define SMEM_SZ 108032

// ---- fragment-ordered weight blob (uint2 units = 8B per lane) --------------
// unit u -> (cs, tile, lane):  u = (cs*TPC + tile)*32 + lane,  TPC = NW/8.
// lane l supplies n = tile*8 + l/4, k0 = cs*16 + (l%4)*2:
//   .x = {W[k0][n], W[k0+1][n]}   .y = {W[k0+8][n], W[k0+9][n]}
// regions (units): L0 @0 (2048, K=32 zero-pad k>=30); L1..7 @2048+(L-1)*16384;
// L8 @116736 (cols 1..256 shifted); Wc0 @133120 (17 cs, K=272 pad k>=268)
#define BLOB_U 141824
__device__ uint2 g_wblob[BLOB_U];

struct Params {
    const float* x; const float* d;
    const float* W[9]; const float* b[9];
    const float* Wc0; const float* bc0;
    const float* Wc1; const float* bc1;
};

__device__ __forceinline__ void mma16816(float c[4], uint32_t a0, uint32_t a1,
                                         uint32_t a2, uint32_t a3,
                                         uint32_t b0, uint32_t b1) {
    asm("mma.sync.aligned.m16n8k16.row.col.f32.f16.f16.f32 "
        "{%0,%1,%2,%3}, {%4,%5,%6,%7}, {%8,%9}, {%0,%1,%2,%3};"
        : "+f"(c[0]), "+f"(c[1]), "+f"(c[2]), "+f"(c[3])
        : "r"(a0), "r"(a1), "r"(a2), "r"(a3), "r"(b0), "r"(b1));
}
__device__ __forceinline__ void ldsm4(uint32_t r[4], uint32_t addr) {
    asm volatile("ldmatrix.sync.aligned.m8n8.x4.shared.b16 {%0,%1,%2,%3}, [%4];"
                 : "=r"(r[0]), "=r"(r[1]), "=r"(r[2]), "=r"(r[3]) : "r"(addr));
}
__device__ __forceinline__ uint32_t pack2(__half a, __half b) {
    return (uint32_t)__half_as_ushort(a) | ((uint32_t)__half_as_ushort(b) << 16);
}
__device__ __forceinline__ void hsplit(float v, __half& h, __half& l) {
    h = __float2half_rn(v);
    l = __float2half_rn(v - __half2float(h));
}
__device__ __forceinline__ uint32_t packsplit(float v0, float v1, uint32_t& lo) {
    __half h0, l0, h1, l1;
    hsplit(v0, h0, l0); hsplit(v1, h1, l1);
    lo = pack2(l0, l1);
    return pack2(h0, h1);
}
#define BAR_N(id, n) asm volatile("bar.sync %0, %1;" :: "r"(id), "n"(n) : "memory")

// ---- prologue: pack all weights into fragment-ordered f16 blob -------------
__global__ void convert_weights(Params p) {
    int u = blockIdx.x * blockDim.x + threadIdx.x;
    if (u >= BLOB_U) return;
    int lane, tg, cs, ldw, shift, Kmax;
    const float* W;
    if (u < 2048) {                        // L0 (TPC=32)
        lane = u & 31; tg = (u >> 5) & 31; cs = u >> 10;
        W = p.W[0]; ldw = 256; shift = 0; Kmax = 30;
    } else if (u < 116736) {               // L1..L7
        int i = u - 2048, L = 1 + i / 16384, r = i & 16383;
        lane = r & 31; tg = (r >> 5) & 31; cs = r >> 10;
        W = p.W[L]; ldw = 256; shift = 0; Kmax = 256;
    } else if (u < 133120) {               // L8 (cols 1..256)
        int r = u - 116736;
        lane = r & 31; tg = (r >> 5) & 31; cs = r >> 10;
        W = p.W[8]; ldw = 257; shift = 1; Kmax = 256;
    } else {                               // Wc0 (TPC=16, 17 cs)
        int r = u - 133120;
        lane = r & 31; tg = (r >> 5) & 15; cs = r >> 9;
        W = p.Wc0; ldw = 128; shift = 0; Kmax = 268;
    }
    int n  = tg * 8 + (lane >> 2);
    int k0 = cs * 16 + (lane & 3) * 2;
    float v0 = (k0     < Kmax) ? __ldg(&W[(size_t)k0 * ldw + n + shift])       : 0.f;
    float v1 = (k0 + 1 < Kmax) ? __ldg(&W[(size_t)(k0 + 1) * ldw + n + shift]) : 0.f;
    float v8 = (k0 + 8 < Kmax) ? __ldg(&W[(size_t)(k0 + 8) * ldw + n + shift]) : 0.f;
    float v9 = (k0 + 9 < Kmax) ? __ldg(&W[(size_t)(k0 + 9) * ldw + n + shift]) : 0.f;
    uint2 o;
    o.x = pack2(__float2half_rn(v0), __float2half_rn(v1));
    o.y = pack2(__float2half_rn(v8), __float2half_rn(v9));
    g_wblob[u] = o;
}

// ---- GEMM: acc = A[64 x K] @ W[K x NW]; direct-LDG B, reg double buffer ----
template<int NTILES>
__device__ __forceinline__ void gemm_ldg(char* g, uint32_t sb,
                                         const uint2* __restrict__ wb, int K,
                                         int lane, int wm, int wn,
                                         float acc[][4]) {
    constexpr int TPC = NTILES * 4;        // tiles per cs across the CTA
#pragma unroll
    for (int i = 0; i < 2 * NTILES; i++)
#pragma unroll
        for (int j = 0; j < 4; j++) acc[i][j] = 0.f;

    const uint32_t a_base = sb + A_HI + (uint32_t)(wm * 32 + (lane & 15)) * SA_B
                          + (uint32_t)(lane >> 4) * 16;
    const uint2* wp = wb + (wn * NTILES) * 32 + lane;
    const int ncs = (K + 15) >> 4;

    uint2 bcur[NTILES], bnxt[NTILES];
#pragma unroll
    for (int j = 0; j < NTILES; j++) bcur[j] = __ldg(wp + j * 32);

#pragma unroll 1
    for (int cs = 0; cs < ncs; cs++) {
        if (cs + 1 < ncs) {
            const uint2* wn2 = wp + (size_t)(cs + 1) * (TPC * 32);
#pragma unroll
            for (int j = 0; j < NTILES; j++) bnxt[j] = __ldg(wn2 + j * 32);
        }
        int kg = cs * 16;
        uint32_t ah[2][4], al[2][4];
        ldsm4(ah[0], a_base + (uint32_t)kg * 2);
        ldsm4(ah[1], a_base + 16 * SA_B + (uint32_t)kg * 2);
        ldsm4(al[0], a_base + (A_LO - A_HI) + (uint32_t)kg * 2);
        ldsm4(al[1], a_base + (A_LO - A_HI) + 16 * SA_B + (uint32_t)kg * 2);
        // term-major: hi-A over all (mt, j), then lo-A (acc RAW distance 16)
#pragma unroll
        for (int mt = 0; mt < 2; mt++)
#pragma unroll
            for (int j = 0; j < NTILES; j++)
                mma16816(acc[mt * NTILES + j],
                         ah[mt][0], ah[mt][1], ah[mt][2], ah[mt][3],
                         bcur[j].x, bcur[j].y);
#pragma unroll
        for (int mt = 0; mt < 2; mt++)
#pragma unroll
            for (int j = 0; j < NTILES; j++)
                mma16816(acc[mt * NTILES + j],
                         al[mt][0], al[mt][1], al[mt][2], al[mt][3],
                         bcur[j].x, bcur[j].y);
#pragma unroll
        for (int j = 0; j < NTILES; j++) bcur[j] = bnxt[j];
    }
}

// ---- epilogue: bias(+ReLU) from global, hi/lo split back into A ------------
// Row-group barriers: A rows [wm*32,+32) touched only by warps sharing wm
// (warps wm, wm+2, wm+4, wm+6 -> 128 threads at named bar 5+wm).
template<int NTILES, bool FULL>
__device__ __forceinline__ void epilogue_A(char* g, int lane, int wm, int wn,
                                           float acc[][4],
                                           const float* __restrict__ bias_g) {
    if (FULL) __syncthreads();
    else      BAR_N(5 + wm, 128);          // row-group gemm A-reads done
    const int g8 = lane >> 2, tig = lane & 3;
#pragma unroll
    for (int mt = 0; mt < 2; mt++) {
#pragma unroll
        for (int nt = 0; nt < NTILES; nt++) {
            int r1 = wm * 32 + mt * 16 + g8, r2 = r1 + 8;
            int cb = wn * (NTILES * 8) + nt * 8 + tig * 2;
            float* a = acc[mt * NTILES + nt];
            float b0 = __ldg(&bias_g[cb]), b1 = __ldg(&bias_g[cb + 1]);
            uint32_t lo, hi;
            hi = packsplit(fmaxf(a[0] + b0, 0.f), fmaxf(a[1] + b1, 0.f), lo);
            *(uint32_t*)(g + A_HI + r1 * SA_B + cb * 2) = hi;
            *(uint32_t*)(g + A_LO + r1 * SA_B + cb * 2) = lo;
            hi = packsplit(fmaxf(a[2] + b0, 0.f), fmaxf(a[3] + b1, 0.f), lo);
            *(uint32_t*)(g + A_HI + r2 * SA_B + cb * 2) = hi;
            *(uint32_t*)(g + A_LO + r2 * SA_B + cb * 2) = lo;
        }
    }
    BAR_N(5 + wm, 128);                    // writes visible to row-group
}

// color epilogue: bias + ReLU -> hc f32 (full syncs)
__device__ __forceinline__ void epilogue_HC(char* g, int lane, int wm, int wn,
                                            float acc[][4],
                                            const float* __restrict__ bias_g) {
    __syncthreads();                       // all groups' A reads done
    const int g8 = lane >> 2, tig = lane & 3;
#pragma unroll
    for (int mt = 0; mt < 2; mt++) {
#pragma unroll
        for (int nt = 0; nt < 4; nt++) {
            int r1 = wm * 32 + mt * 16 + g8, r2 = r1 + 8;
            int cb = wn * 32 + nt * 8 + tig * 2;
            float* a = acc[mt * 4 + nt];
            float b0 = __ldg(&bias_g[cb]), b1 = __ldg(&bias_g[cb + 1]);
            float2 v1 = make_float2(fmaxf(a[0] + b0, 0.f), fmaxf(a[1] + b1, 0.f));
            float2 v2 = make_float2(fmaxf(a[2] + b0, 0.f), fmaxf(a[3] + b1, 0.f));
            *(float2*)(g + HCOFF + r1 * SHC_B + cb * 4) = v1;
            *(float2*)(g + HCOFF + r2 * SHC_B + cb * 4) = v2;
        }
    }
    __syncthreads();
}

// ---- main kernel -----------------------------------------------------------
__global__ void __launch_bounds__(NT, 2)
nerf_hmma_kernel(Params p, float* __restrict__ out, int ns) {
    extern __shared__ char g[];
    uint32_t sb = (uint32_t)__cvta_generic_to_shared(g);
    int t = threadIdx.x, lane = t & 31, w = t >> 5;
    int wm = w & 1, wn = w >> 1;
    int s0 = blockIdx.x * 64;
    float acc[16][4];

    // stage x -> A cols 0..31 (k>=30 zero); 4 threads/row, 8 k each
    {
        int r = t >> 2, q = t & 3;
        const float* xr = p.x + (size_t)(s0 + r) * 30;
#pragma unroll
        for (int pr = 0; pr < 4; pr++) {
            int k = q * 8 + pr * 2;
            float v0 = (k     < 30) ? xr[k]     : 0.f;
            float v1 = (k + 1 < 30) ? xr[k + 1] : 0.f;
            uint32_t lo, hi = packsplit(v0, v1, lo);
            *(uint32_t*)(g + A_HI + r * SA_B + k * 2) = hi;
            *(uint32_t*)(g + A_LO + r * SA_B + k * 2) = lo;
        }
    }
    __syncthreads();

    // layer 0: 30 -> 256
    gemm_ldg<8>(g, sb, g_wblob, 32, lane, wm, wn, acc);
    epilogue_A<8, false>(g, lane, wm, wn, acc, p.b[0]);

    // layers 1..7: 256 -> 256
#pragma unroll 1
    for (int L = 1; L <= 7; L++) {
        gemm_ldg<8>(g, sb, g_wblob + 2048 + (L - 1) * 16384, 256,
                    lane, wm, wn, acc);
        epilogue_A<8, false>(g, lane, wm, wn, acc, p.b[L]);
    }

    // layer 8: 256 -> 257 (GEMM cols 1..256; col 0 = sigma scalar path)
    ((float*)(g + WCOL0))[t] = __ldg(&p.W[8][(size_t)t * 257]);
    gemm_ldg<8>(g, sb, g_wblob + 116736, 256, lane, wm, wn, acc);
    {   // sigma from A (layer-8 input, hi+lo) before epilogue overwrites A
        __syncthreads();                   // all gemm done; WCOL0 visible
        int r = t >> 2, q = t & 3;
        const float* wc = (const float*)(g + WCOL0);
        float s = 0.f;
#pragma unroll 4
        for (int k = q * 64; k < q * 64 + 64; k++) {
            float hv = __half2float(*(const __half*)(g + A_HI + r * SA_B + k * 2))
                     + __half2float(*(const __half*)(g + A_LO + r * SA_B + k * 2));
            s += hv * wc[k];
        }
        s += __shfl_xor_sync(0xffffffffu, s, 1);
        s += __shfl_xor_sync(0xffffffffu, s, 2);
        if (!q && (s0 + r) < ns) out[s0 + r] = fmaxf(s + __ldg(&p.b[8][0]), 0.f);
    }
    epilogue_A<8, true>(g, lane, wm, wn, acc, p.b[8] + 1);  // fx -> A 0..255

    // stage d -> A cols 256..267, zero 268..271
    {
        int r = t >> 2, q = t & 3;
        const float* dr = p.d + (size_t)(s0 + r) * 12;
#pragma unroll
        for (int pr = 0; pr < 2; pr++) {
            int kg = 256 + q * 4 + pr * 2;
            float v0 = (kg     < 268) ? dr[kg - 256]     : 0.f;
            float v1 = (kg + 1 < 268) ? dr[kg + 1 - 256] : 0.f;
            uint32_t lo, hi = packsplit(v0, v1, lo);
            *(uint32_t*)(g + A_HI + r * SA_B + kg * 2) = hi;
            *(uint32_t*)(g + A_LO + r * SA_B + kg * 2) = lo;
        }
    }
    for (int i = t; i < 384; i += NT) ((float*)(g + WC1O))[i] = __ldg(&p.Wc1[i]);
    __syncthreads();                       // d/Wc1 visible to all warps

    // color layer 0: 268 -> 128 (K padded to 272; 17 cs, tail zero-padded)
    gemm_ldg<4>(g, sb, g_wblob + 133120, 272, lane, wm, wn, acc);
    epilogue_HC(g, lane, wm, wn, acc, p.bc0);

    // head: c = relu(hc @ Wc1 + bc1)
    if (t < 192) {
        int r = t / 3, j = t - r * 3;
        const float* hc  = (const float*)(g + HCOFF + r * SHC_B);
        const float* wc1 = (const float*)(g + WC1O);
        float s = 0.f;
#pragma unroll 4
        for (int k = 0; k < 128; k++) s += hc[k] * wc1[k * 3 + j];
        if ((s0 + r) < ns)
            out[(size_t)ns + (size_t)(s0 + r) * 3 + j] = fmaxf(s + __ldg(&p.bc1[j]), 0.f);
    }
}

extern "C" void kernel_launch(void* const* d_in, const int* in_sizes, int n_in,
                              void* d_out, int out_size) {
    Params p;
    p.x = (const float*)d_in[0];
    p.d = (const float*)d_in[1];
    for (int i = 0; i < 9; i++) {
        p.W[i] = (const float*)d_in[2 + 2 * i];
        p.b[i] = (const float*)d_in[3 + 2 * i];
    }
    p.Wc0 = (const float*)d_in[20];
    p.bc0 = (const float*)d_in[21];
    p.Wc1 = (const float*)d_in[22];
    p.bc1 = (const float*)d_in[23];

    int ns = in_sizes[0] / 30;   // 262144
    convert_weights<<<(BLOB_U + 511) / 512, 512>>>(p);
    cudaFuncSetAttribute(nerf_hmma_kernel,
                         cudaFuncAttributeMaxDynamicSharedMemorySize, SMEM_SZ);
    int grid = (ns + 63) / 64;   // 4096
    nerf_hmma_kernel<<<grid, NT, SMEM_SZ>>>(p, (float*)d_out, ns);
}

// round 16
// speedup vs baseline: 1.7266x; 1.7266x over previous
#include <cuda_runtime.h>
#include <cuda_fp16.h>
#include <cstdint>

// ---------------------------------------------------------------------------
// NeRF fused MLP via mma.sync m16n8k16, PURE f16 GEMM (A and B both f16,
// fp32 accum).  Error budget: B-f16 alone measured 1.36e-4 (R13); A-f16 adds
// an independent ~1.4e-4 -> predicted 2-4e-4 vs 1e-3 threshold.
// TM=64/CTA, 256 thr (8 warps, 2x4), 79.4 KB smem -> 2 CTAs/SM.
// W pre-converted once to a __device__ f16 blob in per-chunk [n][k] order;
// per-wn-group cp.async staging (named bars 1-4, 64 thr); ldmatrix frags;
// same-NW cross-layer prefetch; row-group epilogue barriers (5-6, 128 thr).
// ---------------------------------------------------------------------------

#define NT 256

// A: [64][280] halves (single plane), row stride 560 B (bank shift 12)
#define SA_B   560
#define A_HI   0
// W double buffer: single f16 plane, 256 n-rows x 80 B (64 data + 16 pad)
#define W_BASE 35840
#define W_BUFB 20480            // byte stride between buffer 0 and 1
// hc f32 [64][132] overlaid on W region (dead during head)
#define HCOFF  35840
#define SHC_B  528
#define WCOL0  76800
#define WC1O   77824
#define SMEM_SZ 79360

// weight blob layout (halves):
//  L0   @ 0      : 256n x 32k (k>=30 zero)                 = 8192
//  L1-7 @ 8192+(L-1)*65536 : 8 chunks x (256n x 32k)       = 65536 each
//  L8   @ 466944 : cols 1..256 shifted                     = 65536
//  Wc0  @ 532480 : 8 chunks x (128n x 32k) + 1 x (128n x 16k), k>=268 zero
#define BLOB_N 567296
__device__ __half g_whi[BLOB_N];

struct Params {
    const float* x; const float* d;
    const float* W[9]; const float* b[9];
    const float* Wc0; const float* bc0;
    const float* Wc1; const float* bc1;
};

__device__ __forceinline__ void mma16816(float c[4], uint32_t a0, uint32_t a1,
                                         uint32_t a2, uint32_t a3,
                                         uint32_t b0, uint32_t b1) {
    asm("mma.sync.aligned.m16n8k16.row.col.f32.f16.f16.f32 "
        "{%0,%1,%2,%3}, {%4,%5,%6,%7}, {%8,%9}, {%0,%1,%2,%3};"
        : "+f"(c[0]), "+f"(c[1]), "+f"(c[2]), "+f"(c[3])
        : "r"(a0), "r"(a1), "r"(a2), "r"(a3), "r"(b0), "r"(b1));
}
__device__ __forceinline__ void ldsm4(uint32_t r[4], uint32_t addr) {
    asm volatile("ldmatrix.sync.aligned.m8n8.x4.shared.b16 {%0,%1,%2,%3}, [%4];"
                 : "=r"(r[0]), "=r"(r[1]), "=r"(r[2]), "=r"(r[3]) : "r"(addr));
}
__device__ __forceinline__ uint32_t pack2(__half a, __half b) {
    return (uint32_t)__half_as_ushort(a) | ((uint32_t)__half_as_ushort(b) << 16);
}
__device__ __forceinline__ uint32_t packf16(float v0, float v1) {
    return pack2(__float2half_rn(v0), __float2half_rn(v1));
}
#define CP_COMMIT() asm volatile("cp.async.commit_group;")
#define CP_WAIT0()  asm volatile("cp.async.wait_group 0;")
#define BAR_N(id, n) asm volatile("bar.sync %0, %1;" :: "r"(id), "n"(n) : "memory")

// ---- prologue: convert all weights f32 -> f16 blob -------------------------
__global__ void convert_weights(Params p) {
    int idx = blockIdx.x * blockDim.x + threadIdx.x;
    if (idx >= BLOB_N) return;
    float v;
    if (idx < 8192) {                       // L0
        int n = idx >> 5, kk = idx & 31;
        v = (kk < 30) ? __ldg(&p.W[0][kk * 256 + n]) : 0.f;
    } else if (idx < 532480) {              // L1..L8
        int i = idx - 8192;
        int L = 1 + i / 65536;
        int r = i & 65535;
        int gk = (r >> 13) * 32 + (r & 31);
        int n  = (r >> 5) & 255;
        v = (L <= 7) ? __ldg(&p.W[L][(size_t)gk * 256 + n])
                     : __ldg(&p.W[8][(size_t)gk * 257 + n + 1]);
    } else {                                // Wc0
        int i = idx - 532480;
        if (i < 32768) {
            int gk = (i >> 12) * 32 + (i & 31);
            int n  = (i >> 5) & 127;
            v = __ldg(&p.Wc0[(size_t)gk * 128 + n]);
        } else {
            int j = i - 32768;
            int n = j >> 4, gk = 256 + (j & 15);
            v = (gk < 268) ? __ldg(&p.Wc0[(size_t)gk * 128 + n]) : 0.f;
        }
    }
    g_whi[idx] = __float2half_rn(v);
}

// ---- stage a W-slice of one chunk (16B cp.async; 64-thread wn-group) -------
__device__ __forceinline__ void stage_grp(uint32_t dstb, const __half* hs,
                                          int n0, int NG, int kw, int csh,
                                          int tl) {
    int cpr = 1 << csh;                    // 16B copies per row
    int total = NG * cpr;
#pragma unroll 1
    for (int idx = tl; idx < total; idx += 64) {
        int n = n0 + (idx >> csh);
        int j = idx & (cpr - 1);
        const __half* s = hs + n * kw + j * 8;
        uint32_t dd = dstb + n * 80 + j * 16;
        asm volatile("cp.async.cg.shared.global [%0], [%1], 16;"
                     :: "r"(dd), "l"(s));
    }
}

// ---- GEMM: acc = A[64 x K] @ W[K x NW]; decoupled wn-groups + prefetch -----
// Prefetch (next_base>=0) ONLY legal when next layer has the same NW
// (otherwise rows cross wn-group ownership and race: the R11 color bug).
template<int NTILES>
__device__ __forceinline__ void gemm_layer(char* g, uint32_t sb, int base,
                                           int K, int t, int lane, int wm,
                                           int wn, float acc[][4], int& buf,
                                           bool pre, int next_base) {
    constexpr int NW = NTILES * 32;
    constexpr int NG = NW / 4;
#pragma unroll
    for (int i = 0; i < 2 * NTILES; i++)
#pragma unroll
        for (int j = 0; j < 4; j++) acc[i][j] = 0.f;

    const int tl = t & 63;
    const int bar_id = 1 + (t >> 6);       // 1 + wn
    const int n0 = wn * NG;
    const int nch = (K + 31) >> 5;

    // ldmatrix lane bases
    const uint32_t a_base = sb + A_HI + (uint32_t)(wm * 32 + (lane & 15)) * SA_B
                          + (uint32_t)(lane >> 4) * 16;
    const int q = lane >> 3;
    const uint32_t b_lane = (uint32_t)(((lane & 7) + ((q >> 1) << 3)) * 80
                                       + (q & 1) * 16);

    if (!pre) {                            // chunk 0 not prefetched
        int kw = min(32, K);
        stage_grp(sb + W_BASE + (buf & 1) * W_BUFB, g_whi + base,
                  n0, NG, kw, (kw == 32) ? 2 : 1, tl);
        CP_COMMIT();
    }

    auto do_ks = [&](uint32_t wb, int kg, int kl) {
        uint32_t ah[2][4];
        ldsm4(ah[0], a_base + (uint32_t)kg * 2);
        ldsm4(ah[1], a_base + 16 * SA_B + (uint32_t)kg * 2);
#pragma unroll
        for (int ntp = 0; ntp < NTILES / 2; ntp++) {
            uint32_t bb = wb + (uint32_t)((wn * (NTILES * 8) + ntp * 16) * 80)
                        + b_lane + (uint32_t)kl * 2;
            uint32_t bh[4];
            ldsm4(bh, bb);
#pragma unroll
            for (int mt = 0; mt < 2; mt++)
#pragma unroll
                for (int sub = 0; sub < 2; sub++)
                    mma16816(acc[mt * NTILES + 2 * ntp + sub],
                             ah[mt][0], ah[mt][1], ah[mt][2], ah[mt][3],
                             bh[2 * sub], bh[2 * sub + 1]);
        }
    };

#pragma unroll 1
    for (int c = 0; c < nch; c++) {
        CP_WAIT0();                        // chunk c arrived (this thread)
        BAR_N(bar_id, 64);                 // publish; orders c-1 reads too
        if (c + 1 < nch) {
            int kw2 = min(32, K - (c + 1) * 32);
            int off = base + NW * 32 * (c + 1);
            stage_grp(sb + W_BASE + ((buf + c + 1) & 1) * W_BUFB,
                      g_whi + off, n0, NG, kw2, (kw2 == 32) ? 2 : 1, tl);
            CP_COMMIT();
        } else if (next_base >= 0) {       // prefetch next layer chunk 0
            stage_grp(sb + W_BASE + ((buf + nch) & 1) * W_BUFB,
                      g_whi + next_base, n0, NG, 32, 2, tl);
            CP_COMMIT();
        }
        uint32_t wb = sb + W_BASE + (uint32_t)(((buf + c) & 1) * W_BUFB);
        int ksteps = min(32, K - c * 32) >> 4;
        do_ks(wb, c * 32, 0);
        if (ksteps == 2) do_ks(wb, c * 32 + 16, 16);
    }
    buf += nch;
}

// ---- epilogue: bias(+ReLU) from global, f16 back into A --------------------
// Row-group barriers: A rows [wm*32,+32) touched only by warps sharing wm
// (warps wm, wm+2, wm+4, wm+6 -> 128 threads at named bar 5+wm).
template<int NTILES, bool FULL>
__device__ __forceinline__ void epilogue_A(char* g, int lane, int wm, int wn,
                                           float acc[][4],
                                           const float* __restrict__ bias_g) {
    if (FULL) __syncthreads();
    else      BAR_N(5 + wm, 128);          // row-group gemm A-reads done
    const int g8 = lane >> 2, tig = lane & 3;
#pragma unroll
    for (int mt = 0; mt < 2; mt++) {
#pragma unroll
        for (int nt = 0; nt < NTILES; nt++) {
            int r1 = wm * 32 + mt * 16 + g8, r2 = r1 + 8;
            int cb = wn * (NTILES * 8) + nt * 8 + tig * 2;
            float* a = acc[mt * NTILES + nt];
            float b0 = __ldg(&bias_g[cb]), b1 = __ldg(&bias_g[cb + 1]);
            *(uint32_t*)(g + A_HI + r1 * SA_B + cb * 2) =
                packf16(fmaxf(a[0] + b0, 0.f), fmaxf(a[1] + b1, 0.f));
            *(uint32_t*)(g + A_HI + r2 * SA_B + cb * 2) =
                packf16(fmaxf(a[2] + b0, 0.f), fmaxf(a[3] + b1, 0.f));
        }
    }
    BAR_N(5 + wm, 128);                    // writes visible to row-group
}

// color epilogue: bias + ReLU -> hc f32 (overlays W region; full syncs)
__device__ __forceinline__ void epilogue_HC(char* g, int lane, int wm, int wn,
                                            float acc[][4],
                                            const float* __restrict__ bias_g) {
    __syncthreads();                       // all groups' A/W reads done
    const int g8 = lane >> 2, tig = lane & 3;
#pragma unroll
    for (int mt = 0; mt < 2; mt++) {
#pragma unroll
        for (int nt = 0; nt < 4; nt++) {
            int r1 = wm * 32 + mt * 16 + g8, r2 = r1 + 8;
            int cb = wn * 32 + nt * 8 + tig * 2;
            float* a = acc[mt * 4 + nt];
            float b0 = __ldg(&bias_g[cb]), b1 = __ldg(&bias_g[cb + 1]);
            float2 v1 = make_float2(fmaxf(a[0] + b0, 0.f), fmaxf(a[1] + b1, 0.f));
            float2 v2 = make_float2(fmaxf(a[2] + b0, 0.f), fmaxf(a[3] + b1, 0.f));
            *(float2*)(g + HCOFF + r1 * SHC_B + cb * 4) = v1;
            *(float2*)(g + HCOFF + r2 * SHC_B + cb * 4) = v2;
        }
    }
    __syncthreads();
}

// ---- main kernel -----------------------------------------------------------
__global__ void __launch_bounds__(NT, 2)
nerf_hmma_kernel(Params p, float* __restrict__ out, int ns) {
    extern __shared__ char g[];
    uint32_t sb = (uint32_t)__cvta_generic_to_shared(g);
    int t = threadIdx.x, lane = t & 31, w = t >> 5;
    int wm = w & 1, wn = w >> 1;
    int s0 = blockIdx.x * 64;
    float acc[16][4];
    int buf = 0;

    // stage x -> A cols 0..31 (k>=30 zero); 4 threads/row, 8 k each
    {
        int r = t >> 2, q = t & 3;
        const float* xr = p.x + (size_t)(s0 + r) * 30;
#pragma unroll
        for (int pr = 0; pr < 4; pr++) {
            int k = q * 8 + pr * 2;
            float v0 = (k     < 30) ? xr[k]     : 0.f;
            float v1 = (k + 1 < 30) ? xr[k + 1] : 0.f;
            *(uint32_t*)(g + A_HI + r * SA_B + k * 2) = packf16(v0, v1);
        }
    }
    __syncthreads();

    // layer 0: 30 -> 256 (prefetches L1 chunk 0; same NW)
    gemm_layer<8>(g, sb, 0, 32, t, lane, wm, wn, acc, buf, false, 8192);
    epilogue_A<8, false>(g, lane, wm, wn, acc, p.b[0]);

    // layers 1..7: 256 -> 256
#pragma unroll 1
    for (int L = 1; L <= 7; L++) {
        int nb = (L < 7) ? 8192 + L * 65536 : 466944;
        gemm_layer<8>(g, sb, 8192 + (L - 1) * 65536, 256, t, lane, wm, wn,
                      acc, buf, true, nb);
        epilogue_A<8, false>(g, lane, wm, wn, acc, p.b[L]);
    }

    // layer 8: 256 -> 257 (GEMM cols 1..256; col 0 = sigma scalar path)
    // NO prefetch here: next layer has NW=128 (row ownership changes).
    ((float*)(g + WCOL0))[t] = __ldg(&p.W[8][(size_t)t * 257]);
    gemm_layer<8>(g, sb, 466944, 256, t, lane, wm, wn, acc, buf, true, -1);
    {   // sigma from A (layer-8 input, f16) before epilogue overwrites A
        __syncthreads();                   // all gemm done; WCOL0 visible
        int r = t >> 2, q = t & 3;
        const float* wc = (const float*)(g + WCOL0);
        float s = 0.f;
#pragma unroll 4
        for (int k = q * 64; k < q * 64 + 64; k++) {
            float hv = __half2float(*(const __half*)(g + A_HI + r * SA_B + k * 2));
            s += hv * wc[k];
        }
        s += __shfl_xor_sync(0xffffffffu, s, 1);
        s += __shfl_xor_sync(0xffffffffu, s, 2);
        if (!q && (s0 + r) < ns) out[s0 + r] = fmaxf(s + __ldg(&p.b[8][0]), 0.f);
    }
    epilogue_A<8, true>(g, lane, wm, wn, acc, p.b[8] + 1);  // fx -> A 0..255

    // stage d -> A cols 256..267, zero 268..271
    {
        int r = t >> 2, q = t & 3;
        const float* dr = p.d + (size_t)(s0 + r) * 12;
#pragma unroll
        for (int pr = 0; pr < 2; pr++) {
            int kg = 256 + q * 4 + pr * 2;
            float v0 = (kg     < 268) ? dr[kg - 256]     : 0.f;
            float v1 = (kg + 1 < 268) ? dr[kg + 1 - 256] : 0.f;
            *(uint32_t*)(g + A_HI + r * SA_B + kg * 2) = packf16(v0, v1);
        }
    }
    for (int i = t; i < 384; i += NT) ((float*)(g + WC1O))[i] = __ldg(&p.Wc1[i]);
    __syncthreads();                       // all writes visible; all L8 W
                                           // reads done before color staging

    // color layer 0: 268 -> 128 (K padded to 272; stages own chunk 0)
    gemm_layer<4>(g, sb, 532480, 272, t, lane, wm, wn, acc, buf, false, -1);
    epilogue_HC(g, lane, wm, wn, acc, p.bc0);

    // head: c = relu(hc @ Wc1 + bc1)
    if (t < 192) {
        int r = t / 3, j = t - r * 3;
        const float* hc  = (const float*)(g + HCOFF + r * SHC_B);
        const float* wc1 = (const float*)(g + WC1O);
        float s = 0.f;
#pragma unroll 4
        for (int k = 0; k < 128; k++) s += hc[k] * wc1[k * 3 + j];
        if ((s0 + r) < ns)
            out[(size_t)ns + (size_t)(s0 + r) * 3 + j] = fmaxf(s + __ldg(&p.bc1[j]), 0.f);
    }
}

extern "C" void kernel_launch(void* const* d_in, const int* in_sizes, int n_in,
                              void* d_out, int out_size) {
    Params p;
    p.x = (const float*)d_in[0];
    p.d = (const float*)d_in[1];
    for (int i = 0; i < 9; i++) {
        p.W[i] = (const float*)d_in[2 + 2 * i];
        p.b[i] = (const float*)d_in[3 + 2 * i];
    }
    p.Wc0 = (const float*)d_in[20];
    p.bc0 = (const float*)d_in[21];
    p.Wc1 = (const float*)d_in[22];
    p.bc1 = (const float*)d_in[23];

    int ns = in_sizes[0] / 30;   // 262144
    convert_weights<<<(BLOB_N + 511) / 512, 512>>>(p);
    cudaFuncSetAttribute(nerf_hmma_kernel,
                         cudaFuncAttributeMaxDynamicSharedMemorySize, SMEM_SZ);
    int grid = (ns + 63) / 64;   // 4096
    nerf_hmma_kernel<<<grid, NT, SMEM_SZ>>>(p, (float*)d_out, ns);
}